// round 8
// baseline (speedup 1.0000x reference)
#include <cuda_runtime.h>
#include <cuda_bf16.h>
#include <cstdint>

// Problem: S=8, N=2048, D=256
//   qt0[s,j,d] = sum_e tensor0[s,j,e] * kernel[d,e]
//   out[s,i,j] = sum_d tensor1[s,i,d] * qt0[s,j,d] + bias
//
// Split fp32 x = h + l (h = trunc-to-bf16, l = rn(x-h)); gmem stores rows as
// [h(256) | l(256)] bf16. Hot loop: Ah*Bh + Al*Bh + Ah*Bl via mma.sync bf16,
// TERM-MAJOR ordering so consecutive HMMAs hit distinct accumulators (no RAW).

#define BM 128
#define BN 128
#define NTHREADS 256
#define ROWB 80                      // padded smem row stride
#define TILE_B (128 * ROWB)          // 10240 per tile
#define STAGE_BYTES (4 * TILE_B)     // Ah, Al, Bh, Bl
#define SMEM_BYTES (2 * STAGE_BYTES) // 81920

static const int S_ = 8;
static const int N_ = 2048;
static const int D_ = 256;
static const int K2 = 512;           // [h | l]

__device__ __nv_bfloat16 g_t0hl[8 * 2048 * 512];
__device__ __nv_bfloat16 g_t1hl[8 * 2048 * 512];
__device__ __nv_bfloat16 g_khl[256 * 512];
__device__ __nv_bfloat16 g_qt0hl[8 * 2048 * 512];

__device__ __forceinline__ uint32_t smem_u32(const void* p) {
    uint32_t a;
    asm("{ .reg .u64 t; cvta.to.shared.u64 t, %1; cvt.u32.u64 %0, t; }" : "=r"(a) : "l"(p));
    return a;
}
__device__ __forceinline__ void ldsm4(uint32_t* r, uint32_t addr) {
    asm volatile("ldmatrix.sync.aligned.m8n8.x4.shared.b16 {%0,%1,%2,%3}, [%4];"
                 : "=r"(r[0]), "=r"(r[1]), "=r"(r[2]), "=r"(r[3]) : "r"(addr));
}
__device__ __forceinline__ void mma16816(float* c, const uint32_t* a, uint32_t b0, uint32_t b1) {
    asm volatile("mma.sync.aligned.m16n8k16.row.col.f32.bf16.bf16.f32 "
                 "{%0,%1,%2,%3}, {%4,%5,%6,%7}, {%8,%9}, {%0,%1,%2,%3};"
                 : "+f"(c[0]), "+f"(c[1]), "+f"(c[2]), "+f"(c[3])
                 : "r"(a[0]), "r"(a[1]), "r"(a[2]), "r"(a[3]), "r"(b0), "r"(b1));
}
__device__ __forceinline__ uint32_t cvt_bf16x2(float hi, float lo) {
    uint32_t d;
    asm("cvt.rn.bf16x2.f32 %0, %1, %2;" : "=r"(d) : "f"(hi), "f"(lo));
    return d;
}
__device__ __forceinline__ void cp16(uint32_t dst, const void* src) {
    asm volatile("cp.async.cg.shared.global [%0], [%1], 16;" :: "r"(dst), "l"(src));
}

// ---- pre-pass: fp32 [rows, D] -> bf16 [rows, 2D] = [h | l] ----
__global__ void split_hl_kernel(const float* __restrict__ src,
                                __nv_bfloat16* __restrict__ dst,
                                int total4, int Dq)
{
    int idx = blockIdx.x * blockDim.x + threadIdx.x;
    if (idx >= total4) return;
    int row = idx / Dq;
    int g = idx - row * Dq;
    float4 v = ((const float4*)src)[idx];
    uint32_t xb = __float_as_uint(v.x), yb = __float_as_uint(v.y);
    uint32_t zb = __float_as_uint(v.z), wb = __float_as_uint(v.w);
    uint2 hp = make_uint2(__byte_perm(xb, yb, 0x7632), __byte_perm(zb, wb, 0x7632));
    float l0 = v.x - __uint_as_float(xb & 0xFFFF0000u);
    float l1 = v.y - __uint_as_float(yb & 0xFFFF0000u);
    float l2 = v.z - __uint_as_float(zb & 0xFFFF0000u);
    float l3 = v.w - __uint_as_float(wb & 0xFFFF0000u);
    uint2 lp = make_uint2(cvt_bf16x2(l1, l0), cvt_bf16x2(l3, l2));
    uint2* drow = (uint2*)(dst + (long)row * (2 * Dq * 4));
    drow[g] = hp;
    drow[Dq + g] = lp;
}

// ---- GEMM: C[b,m,n] = sum_d A[b,m,d]*B[b,n,d]; A,B bf16 [rows, K2] = [h|l] ----
__global__ __launch_bounds__(NTHREADS, 2)
void gemm_hl_kernel(const __nv_bfloat16* __restrict__ A,
                    const __nv_bfloat16* __restrict__ B,
                    void* __restrict__ Cv,
                    int ldC,
                    long strideA, long strideB, long strideC,
                    const float* __restrict__ bias_ptr, int epi_hl)
{
    extern __shared__ __align__(16) char smem[];
    const uint32_t sbase = smem_u32(smem);

    const int tid  = threadIdx.x;
    const int lane = tid & 31;
    const int wid  = tid >> 5;        // 0..7
    const int wm   = wid & 1;         // 2 warps along M (64 rows)
    const int wn   = wid >> 1;        // 4 warps along N (32 cols)
    const int m0   = blockIdx.y * BM;
    const int n0   = blockIdx.x * BN;
    const int b    = blockIdx.z;

    const char* Ab = (const char*)(A + (long)b * strideA + (long)m0 * K2);
    const char* Bb = (const char*)(B + (long)b * strideB + (long)n0 * K2);
    const int rowBytes = K2 * 2;      // 1024
    const int lHalf = D_ * 2;         // 512

    float acc[4][4][4];
    #pragma unroll
    for (int mi = 0; mi < 4; mi++)
        #pragma unroll
        for (int nf = 0; nf < 4; nf++)
            #pragma unroll
            for (int j = 0; j < 4; j++)
                acc[mi][nf][j] = 0.0f;

    const int nchunk = D_ / 32;       // 8

    auto issue_stage = [&](int slot, int c) {
        const int kb = c * 64;
        const uint32_t st = sbase + slot * STAGE_BYTES;
        #pragma unroll
        for (int i = 0; i < 2; i++) {
            int q = tid + NTHREADS * i;
            int row = q >> 2, qd = (q & 3) * 16;
            const char* arow = Ab + (long)row * rowBytes + kb + qd;
            const char* brow = Bb + (long)row * rowBytes + kb + qd;
            uint32_t so = row * ROWB + qd;
            cp16(st + so,              arow);          // Ah
            cp16(st + TILE_B + so,     arow + lHalf);  // Al
            cp16(st + 2 * TILE_B + so, brow);          // Bh
            cp16(st + 3 * TILE_B + so, brow + lHalf);  // Bl
        }
        asm volatile("cp.async.commit_group;" ::: "memory");
    };

    issue_stage(0, 0);

    const uint32_t lmOff = (uint32_t)((lane & 15) * ROWB + (lane >> 4) * 16);
    const uint32_t aOff = (uint32_t)(wm * 64 * ROWB) + lmOff;
    const uint32_t bOff = (uint32_t)(2 * TILE_B + wn * 32 * ROWB) + lmOff;

    for (int c = 0; c < nchunk; c++) {
        if (c + 1 < nchunk) {
            issue_stage((c + 1) & 1, c + 1);
            asm volatile("cp.async.wait_group 1;" ::: "memory");
        } else {
            asm volatile("cp.async.wait_group 0;" ::: "memory");
        }
        __syncthreads();

        const uint32_t st = sbase + (c & 1) * STAGE_BYTES;
        const uint32_t sA = st + aOff;
        const uint32_t sB = st + bOff;

        #pragma unroll
        for (int ks = 0; ks < 2; ks++) {
            const uint32_t ko = ks * 32;   // 16 bf16 = 32B
            uint32_t aH[4][4], aL[4][4], bH[2][4], bL[2][4];

            // load H fragments first, fire the HH burst while L loads land
            #pragma unroll
            for (int mi = 0; mi < 4; mi++) ldsm4(aH[mi], sA + mi * 16 * ROWB + ko);
            #pragma unroll
            for (int nb = 0; nb < 2; nb++) ldsm4(bH[nb], sB + nb * 16 * ROWB + ko);
            #pragma unroll
            for (int mi = 0; mi < 4; mi++) ldsm4(aL[mi], sA + TILE_B + mi * 16 * ROWB + ko);
            #pragma unroll
            for (int nb = 0; nb < 2; nb++) ldsm4(bL[nb], sB + TILE_B + nb * 16 * ROWB + ko);

            // term-major: 16 independent MMAs per burst (distinct accumulators)
            #pragma unroll
            for (int mi = 0; mi < 4; mi++)
                #pragma unroll
                for (int nf = 0; nf < 4; nf++)
                    mma16816(acc[mi][nf], aH[mi], bH[nf >> 1][nf & 1], bH[nf >> 1][(nf & 1) + 2]);
            #pragma unroll
            for (int mi = 0; mi < 4; mi++)
                #pragma unroll
                for (int nf = 0; nf < 4; nf++)
                    mma16816(acc[mi][nf], aL[mi], bH[nf >> 1][nf & 1], bH[nf >> 1][(nf & 1) + 2]);
            #pragma unroll
            for (int mi = 0; mi < 4; mi++)
                #pragma unroll
                for (int nf = 0; nf < 4; nf++)
                    mma16816(acc[mi][nf], aH[mi], bL[nf >> 1][nf & 1], bL[nf >> 1][(nf & 1) + 2]);
        }
        __syncthreads();
    }

    // ---------------- epilogue ----------------
    const int rbase = wm * 64 + (lane >> 2);
    const int cbase = wn * 32 + (lane & 3) * 2;

    if (!epi_hl) {
        float* Cb = (float*)Cv + (long)b * strideC;
        const float bv = bias_ptr ? bias_ptr[0] : 0.0f;
        #pragma unroll
        for (int mi = 0; mi < 4; mi++) {
            #pragma unroll
            for (int nf = 0; nf < 4; nf++) {
                const int r = m0 + rbase + mi * 16;
                const int cc = n0 + cbase + nf * 8;
                float2 v0 = make_float2(acc[mi][nf][0] + bv, acc[mi][nf][1] + bv);
                float2 v1 = make_float2(acc[mi][nf][2] + bv, acc[mi][nf][3] + bv);
                *(float2*)(Cb + (long)r * ldC + cc)       = v0;
                *(float2*)(Cb + (long)(r + 8) * ldC + cc) = v1;
            }
        }
    } else {
        __nv_bfloat16* Cb = (__nv_bfloat16*)Cv;
        #pragma unroll
        for (int mi = 0; mi < 4; mi++) {
            #pragma unroll
            for (int nf = 0; nf < 4; nf++) {
                const int cc = n0 + cbase + nf * 8;
                #pragma unroll
                for (int half = 0; half < 2; half++) {
                    const int r = m0 + rbase + mi * 16 + half * 8;
                    float f0 = acc[mi][nf][2 * half + 0];
                    float f1 = acc[mi][nf][2 * half + 1];
                    uint32_t b0 = __float_as_uint(f0), b1 = __float_as_uint(f1);
                    uint32_t hp = __byte_perm(b0, b1, 0x7632);
                    float l0 = f0 - __uint_as_float(b0 & 0xFFFF0000u);
                    float l1 = f1 - __uint_as_float(b1 & 0xFFFF0000u);
                    uint32_t lp = cvt_bf16x2(l1, l0);
                    __nv_bfloat16* row = Cb + (long)r * (2 * ldC);
                    *(uint32_t*)(row + cc)       = hp;
                    *(uint32_t*)(row + ldC + cc) = lp;
                }
            }
        }
    }
}

extern "C" void kernel_launch(void* const* d_in, const int* in_sizes, int n_in,
                              void* d_out, int out_size)
{
    const float* tensor0 = (const float*)d_in[0];
    const float* tensor1 = (const float*)d_in[1];
    const float* kernelw = (const float*)d_in[2];
    const float* bias    = (const float*)d_in[3];
    float* out = (float*)d_out;

    __nv_bfloat16 *t0hl, *t1hl, *khl, *qt0hl;
    cudaGetSymbolAddress((void**)&t0hl, g_t0hl);
    cudaGetSymbolAddress((void**)&t1hl, g_t1hl);
    cudaGetSymbolAddress((void**)&khl, g_khl);
    cudaGetSymbolAddress((void**)&qt0hl, g_qt0hl);

    cudaFuncSetAttribute(gemm_hl_kernel,
                         cudaFuncAttributeMaxDynamicSharedMemorySize, SMEM_BYTES);

    const int Dq = D_ / 4;
    {
        int t4a = S_ * N_ * D_ / 4;
        split_hl_kernel<<<(t4a + 255) / 256, 256>>>(tensor0, t0hl, t4a, Dq);
        split_hl_kernel<<<(t4a + 255) / 256, 256>>>(tensor1, t1hl, t4a, Dq);
        int t4k = D_ * D_ / 4;
        split_hl_kernel<<<(t4k + 255) / 256, 256>>>(kernelw, khl, t4k, Dq);
    }

    // GEMM1: qt0 = t0 @ kernel^T -> [h|l] bf16
    {
        dim3 grid(D_ / BN, (S_ * N_) / BM, 1);
        gemm_hl_kernel<<<grid, NTHREADS, SMEM_BYTES>>>(
            t0hl, khl, qt0hl, D_, 0, 0, 0, nullptr, 1);
    }
    // GEMM2: out = t1 @ qt0^T + bias
    {
        dim3 grid(N_ / BN, N_ / BM, S_);
        gemm_hl_kernel<<<grid, NTHREADS, SMEM_BYTES>>>(
            t1hl, qt0hl, out, N_,
            (long)N_ * K2, (long)N_ * K2, (long)N_ * N_, bias, 0);
    }
}

// round 9
// speedup vs baseline: 1.4802x; 1.4802x over previous
#include <cuda_runtime.h>
#include <cuda_fp16.h>
#include <cstdint>

// Problem: S=8, N=2048, D=256
//   qt0[s,j,d] = sum_e tensor0[s,j,e] * kernel[d,e]
//   out[s,i,j] = sum_d tensor1[s,i,d] * qt0[s,j,d] + bias
//
// 2-term fp16 split: x = h + l (h = fp16_rn(x), l = fp16_rn(x - h)).
//   x*y ~= h_x*h_y + l_x*h_y     (B side keeps h only; dropped h*l' ~ 2^-12)
// A operands stored [h(256) | l(256)] fp16; B operands h-only (256 fp16).
// Hot loop: cp.async (3-stage, 1 barrier/chunk) + ldmatrix + mma.sync.m16n8k16.f16.

#define BM 128
#define BN 128
#define NTHREADS 256
#define ROWB 80                        // padded smem row stride (64B data + 16B)
#define TILE_B (128 * ROWB)            // 10240
#define STAGE_BYTES (3 * TILE_B)       // Ah, Al, Bh
#define SMEM_BYTES (3 * STAGE_BYTES)   // 92160 (3 stages) -> 2 CTAs/SM

static const int S_ = 8;
static const int N_ = 2048;
static const int D_ = 256;
static const int K2 = 512;             // A row: [h | l]

// device scratch (no allocs): 16+16+0.125+8 MB
__device__ __half g_t0hl[8 * 2048 * 512];
__device__ __half g_t1hl[8 * 2048 * 512];
__device__ __half g_kh[256 * 256];
__device__ __half g_qt0h[8 * 2048 * 256];

__device__ __forceinline__ uint32_t smem_u32(const void* p) {
    uint32_t a;
    asm("{ .reg .u64 t; cvta.to.shared.u64 t, %1; cvt.u32.u64 %0, t; }" : "=r"(a) : "l"(p));
    return a;
}
__device__ __forceinline__ void ldsm4(uint32_t* r, uint32_t addr) {
    asm volatile("ldmatrix.sync.aligned.m8n8.x4.shared.b16 {%0,%1,%2,%3}, [%4];"
                 : "=r"(r[0]), "=r"(r[1]), "=r"(r[2]), "=r"(r[3]) : "r"(addr));
}
__device__ __forceinline__ void mma16816(float* c, const uint32_t* a, uint32_t b0, uint32_t b1) {
    asm volatile("mma.sync.aligned.m16n8k16.row.col.f32.f16.f16.f32 "
                 "{%0,%1,%2,%3}, {%4,%5,%6,%7}, {%8,%9}, {%0,%1,%2,%3};"
                 : "+f"(c[0]), "+f"(c[1]), "+f"(c[2]), "+f"(c[3])
                 : "r"(a[0]), "r"(a[1]), "r"(a[2]), "r"(a[3]), "r"(b0), "r"(b1));
}
__device__ __forceinline__ void cp16(uint32_t dst, const void* src) {
    asm volatile("cp.async.cg.shared.global [%0], [%1], 16;" :: "r"(dst), "l"(src));
}

// ---- pre-pass: fp32 [rows, D] -> fp16.
// mode 0: dst rows of 2D = [h | l].   mode 1: dst rows of D = h only.
__global__ void split_kernel(const float* __restrict__ src,
                             __half* __restrict__ dst,
                             int total4, int Dq, int mode)
{
    int idx = blockIdx.x * blockDim.x + threadIdx.x;
    if (idx >= total4) return;
    int row = idx / Dq;
    int g = idx - row * Dq;
    float4 v = ((const float4*)src)[idx];
    __half h0 = __float2half_rn(v.x), h1 = __float2half_rn(v.y);
    __half h2 = __float2half_rn(v.z), h3 = __float2half_rn(v.w);
    __half2 hp0 = __halves2half2(h0, h1);
    __half2 hp1 = __halves2half2(h2, h3);
    if (mode == 1) {
        __half2* drow = (__half2*)(dst + (long)row * (Dq * 4));
        drow[2 * g]     = hp0;
        drow[2 * g + 1] = hp1;
    } else {
        __half l0 = __float2half_rn(v.x - __half2float(h0));
        __half l1 = __float2half_rn(v.y - __half2float(h1));
        __half l2 = __float2half_rn(v.z - __half2float(h2));
        __half l3 = __float2half_rn(v.w - __half2float(h3));
        __half2* drow = (__half2*)(dst + (long)row * (2 * Dq * 4));
        drow[2 * g]     = hp0;
        drow[2 * g + 1] = hp1;
        drow[2 * Dq + 2 * g]     = __halves2half2(l0, l1);
        drow[2 * Dq + 2 * g + 1] = __halves2half2(l2, l3);
    }
}

// ---- GEMM: C[b,m,n] = sum_d A[b,m,d]*B[b,n,d]
// A fp16 [rows, 512] = [h|l]; B fp16 [rows, 256] = h.
// epi_hl == 0: C fp32 [.., M, ldC] + bias.   epi_hl == 1: C fp16 h [M, ldC].
__global__ __launch_bounds__(NTHREADS, 2)
void gemm_hl_kernel(const __half* __restrict__ A,
                    const __half* __restrict__ B,
                    void* __restrict__ Cv,
                    int ldC,
                    long strideA, long strideB, long strideC,
                    const float* __restrict__ bias_ptr, int epi_hl)
{
    extern __shared__ __align__(16) char smem[];
    const uint32_t sbase = smem_u32(smem);

    const int tid  = threadIdx.x;
    const int lane = tid & 31;
    const int wid  = tid >> 5;        // 0..7
    const int wm   = wid & 3;         // 4 warps along M (32 rows each)
    const int wn   = wid >> 2;        // 2 warps along N (64 cols each)
    const int m0   = blockIdx.y * BM;
    const int n0   = blockIdx.x * BN;
    const int b    = blockIdx.z;

    const char* Ab = (const char*)(A + (long)b * strideA + (long)m0 * K2);
    const char* Bb = (const char*)(B + (long)b * strideB + (long)n0 * D_);
    const int aRowB = K2 * 2;         // 1024
    const int bRowB = D_ * 2;         // 512
    const int lHalf = D_ * 2;         // 512: l offset within A row

    float acc[2][8][4];
    #pragma unroll
    for (int mi = 0; mi < 2; mi++)
        #pragma unroll
        for (int nf = 0; nf < 8; nf++)
            #pragma unroll
            for (int j = 0; j < 4; j++)
                acc[mi][nf][j] = 0.0f;

    const int nchunk = D_ / 32;       // 8 chunks of 64B per row

    auto issue_stage = [&](int slot, int c) {
        const int kb = c * 64;
        const uint32_t st = sbase + slot * STAGE_BYTES;
        #pragma unroll
        for (int i = 0; i < 2; i++) {
            int q = tid + NTHREADS * i;       // 0..511
            int row = q >> 2, qd = (q & 3) * 16;
            const char* arow = Ab + (long)row * aRowB + kb + qd;
            const char* brow = Bb + (long)row * bRowB + kb + qd;
            uint32_t so = row * ROWB + qd;
            cp16(st + so,              arow);          // Ah
            cp16(st + TILE_B + so,     arow + lHalf);  // Al
            cp16(st + 2 * TILE_B + so, brow);          // Bh
        }
        asm volatile("cp.async.commit_group;" ::: "memory");
    };

    issue_stage(0, 0);
    issue_stage(1, 1);

    const uint32_t lmOff = (uint32_t)((lane & 15) * ROWB + (lane >> 4) * 16);
    const uint32_t aOff = (uint32_t)(wm * 32 * ROWB) + lmOff;
    const uint32_t bOff = (uint32_t)(2 * TILE_B + wn * 64 * ROWB) + lmOff;

    for (int c = 0; c < nchunk; c++) {
        if (c == nchunk - 1) {
            asm volatile("cp.async.wait_group 0;" ::: "memory");
        } else {
            asm volatile("cp.async.wait_group 1;" ::: "memory");
        }
        __syncthreads();
        // safe to refill slot (c+2)%3: its previous readers (stage c-1) finished
        if (c + 2 < nchunk) issue_stage((c + 2) % 3, c + 2);

        const uint32_t st = sbase + (c % 3) * STAGE_BYTES;
        const uint32_t sA = st + aOff;
        const uint32_t sB = st + bOff;

        #pragma unroll
        for (int ks = 0; ks < 2; ks++) {
            const uint32_t ko = ks * 32;   // 16 fp16 = 32B
            uint32_t aH[2][4], aL[2][4], bF[4][4];
            #pragma unroll
            for (int mi = 0; mi < 2; mi++) ldsm4(aH[mi], sA + mi * 16 * ROWB + ko);
            #pragma unroll
            for (int nb = 0; nb < 4; nb++) ldsm4(bF[nb], sB + nb * 16 * ROWB + ko);
            #pragma unroll
            for (int mi = 0; mi < 2; mi++) ldsm4(aL[mi], sA + TILE_B + mi * 16 * ROWB + ko);

            // 16 independent MMAs per term burst
            #pragma unroll
            for (int mi = 0; mi < 2; mi++)
                #pragma unroll
                for (int nf = 0; nf < 8; nf++)
                    mma16816(acc[mi][nf], aH[mi], bF[nf >> 1][nf & 1], bF[nf >> 1][(nf & 1) + 2]);
            #pragma unroll
            for (int mi = 0; mi < 2; mi++)
                #pragma unroll
                for (int nf = 0; nf < 8; nf++)
                    mma16816(acc[mi][nf], aL[mi], bF[nf >> 1][nf & 1], bF[nf >> 1][(nf & 1) + 2]);
        }
    }

    // ---------------- epilogue ----------------
    const int rbase = wm * 32 + (lane >> 2);
    const int cbase = wn * 64 + (lane & 3) * 2;

    if (!epi_hl) {
        float* Cb = (float*)Cv + (long)b * strideC;
        const float bv = bias_ptr ? bias_ptr[0] : 0.0f;
        #pragma unroll
        for (int mi = 0; mi < 2; mi++) {
            #pragma unroll
            for (int nf = 0; nf < 8; nf++) {
                const int r = m0 + rbase + mi * 16;
                const int cc = n0 + cbase + nf * 8;
                float2 v0 = make_float2(acc[mi][nf][0] + bv, acc[mi][nf][1] + bv);
                float2 v1 = make_float2(acc[mi][nf][2] + bv, acc[mi][nf][3] + bv);
                *(float2*)(Cb + (long)r * ldC + cc)       = v0;
                *(float2*)(Cb + (long)(r + 8) * ldC + cc) = v1;
            }
        }
    } else {
        __half* Cb = (__half*)Cv;
        #pragma unroll
        for (int mi = 0; mi < 2; mi++) {
            #pragma unroll
            for (int nf = 0; nf < 8; nf++) {
                const int cc = n0 + cbase + nf * 8;
                #pragma unroll
                for (int half_i = 0; half_i < 2; half_i++) {
                    const int r = m0 + rbase + mi * 16 + half_i * 8;
                    __half2 hp = __floats2half2_rn(acc[mi][nf][2 * half_i + 0],
                                                   acc[mi][nf][2 * half_i + 1]);
                    *(__half2*)(Cb + (long)r * ldC + cc) = hp;
                }
            }
        }
    }
}

extern "C" void kernel_launch(void* const* d_in, const int* in_sizes, int n_in,
                              void* d_out, int out_size)
{
    const float* tensor0 = (const float*)d_in[0];
    const float* tensor1 = (const float*)d_in[1];
    const float* kernelw = (const float*)d_in[2];
    const float* bias    = (const float*)d_in[3];
    float* out = (float*)d_out;

    __half *t0hl, *t1hl, *kh, *qt0h;
    cudaGetSymbolAddress((void**)&t0hl, g_t0hl);
    cudaGetSymbolAddress((void**)&t1hl, g_t1hl);
    cudaGetSymbolAddress((void**)&kh, g_kh);
    cudaGetSymbolAddress((void**)&qt0h, g_qt0h);

    cudaFuncSetAttribute(gemm_hl_kernel,
                         cudaFuncAttributeMaxDynamicSharedMemorySize, SMEM_BYTES);

    const int Dq = D_ / 4;
    {
        int t4a = S_ * N_ * D_ / 4;
        split_kernel<<<(t4a + 255) / 256, 256>>>(tensor0, t0hl, t4a, Dq, 0);
        split_kernel<<<(t4a + 255) / 256, 256>>>(tensor1, t1hl, t4a, Dq, 0);
        int t4k = D_ * D_ / 4;
        split_kernel<<<(t4k + 255) / 256, 256>>>(kernelw, kh, t4k, Dq, 1);
    }

    // GEMM1: qt0h[j,d] = fp16( sum_e t0[j,e]*kernel[d,e] );  A=[h|l], B=kernel h
    {
        dim3 grid(D_ / BN, (S_ * N_) / BM, 1);     // (2, 128, 1)
        gemm_hl_kernel<<<grid, NTHREADS, SMEM_BYTES>>>(
            t0hl, kh, qt0h, D_, 0, 0, 0, nullptr, 1);
    }
    // GEMM2: out = t1 @ qt0^T + bias;  A=[h|l], B=qt0 h
    {
        dim3 grid(N_ / BN, N_ / BM, S_);           // (16, 16, 8)
        gemm_hl_kernel<<<grid, NTHREADS, SMEM_BYTES>>>(
            t1hl, qt0h, out, N_,
            (long)N_ * K2, (long)N_ * D_, (long)N_ * N_, bias, 0);
    }
}

// round 10
// speedup vs baseline: 1.8313x; 1.2372x over previous
#include <cuda_runtime.h>
#include <cuda_fp16.h>
#include <cstdint>

// Problem: S=8, N=2048, D=256
//   qt0[s,j,d] = sum_e tensor0[s,j,e] * kernel[d,e]
//   out[s,i,j] = sum_d tensor1[s,i,d] * qt0[s,j,d] + bias
//
// fp16 split pipeline:
//   GEMM1 (2-term): qt0_h = fp16( t0_h*k_h + t0_l*k_h )     [k l-term dropped]
//   GEMM2 (1-term): out   = t1_h * qt0_h + bias             [t1 l-term dropped]
// error budget ~3.8e-4 rms vs 1e-3 threshold.

#define BM 128
#define BN 128
#define NTHREADS 256
#define ROWB 80                        // padded smem row stride (64B data + 16B)
#define TILE_B (128 * ROWB)            // 10240
#define STAGE_BYTES (3 * TILE_B)       // Ah, Al, Bh slots (Al unused in 1-term mode)
#define SMEM_BYTES (3 * STAGE_BYTES)   // 92160 -> 2 CTAs/SM

static const int S_ = 8;
static const int N_ = 2048;
static const int D_ = 256;
static const int K2 = 512;             // two-term A row: [h | l]

// device scratch (no allocs): 16 + 8 + 0.125 + 8 MB
__device__ __half g_t0hl[8 * 2048 * 512];
__device__ __half g_t1h[8 * 2048 * 256];
__device__ __half g_kh[256 * 256];
__device__ __half g_qt0h[8 * 2048 * 256];

__device__ __forceinline__ uint32_t smem_u32(const void* p) {
    uint32_t a;
    asm("{ .reg .u64 t; cvta.to.shared.u64 t, %1; cvt.u32.u64 %0, t; }" : "=r"(a) : "l"(p));
    return a;
}
__device__ __forceinline__ void ldsm4(uint32_t* r, uint32_t addr) {
    asm volatile("ldmatrix.sync.aligned.m8n8.x4.shared.b16 {%0,%1,%2,%3}, [%4];"
                 : "=r"(r[0]), "=r"(r[1]), "=r"(r[2]), "=r"(r[3]) : "r"(addr));
}
__device__ __forceinline__ void mma16816(float* c, const uint32_t* a, uint32_t b0, uint32_t b1) {
    asm volatile("mma.sync.aligned.m16n8k16.row.col.f32.f16.f16.f32 "
                 "{%0,%1,%2,%3}, {%4,%5,%6,%7}, {%8,%9}, {%0,%1,%2,%3};"
                 : "+f"(c[0]), "+f"(c[1]), "+f"(c[2]), "+f"(c[3])
                 : "r"(a[0]), "r"(a[1]), "r"(a[2]), "r"(a[3]), "r"(b0), "r"(b1));
}
__device__ __forceinline__ void cp16(uint32_t dst, const void* src) {
    asm volatile("cp.async.cg.shared.global [%0], [%1], 16;" :: "r"(dst), "l"(src));
}

// ---- pre-pass: fp32 [rows, D] -> fp16.
// mode 0: dst rows of 2D = [h | l].   mode 1: dst rows of D = h only.
__global__ void split_kernel(const float* __restrict__ src,
                             __half* __restrict__ dst,
                             int total4, int Dq, int mode)
{
    int idx = blockIdx.x * blockDim.x + threadIdx.x;
    if (idx >= total4) return;
    int row = idx / Dq;
    int g = idx - row * Dq;
    float4 v = ((const float4*)src)[idx];
    __half h0 = __float2half_rn(v.x), h1 = __float2half_rn(v.y);
    __half h2 = __float2half_rn(v.z), h3 = __float2half_rn(v.w);
    __half2 hp0 = __halves2half2(h0, h1);
    __half2 hp1 = __halves2half2(h2, h3);
    if (mode == 1) {
        __half2* drow = (__half2*)(dst + (long)row * (Dq * 4));
        drow[2 * g]     = hp0;
        drow[2 * g + 1] = hp1;
    } else {
        __half l0 = __float2half_rn(v.x - __half2float(h0));
        __half l1 = __float2half_rn(v.y - __half2float(h1));
        __half l2 = __float2half_rn(v.z - __half2float(h2));
        __half l3 = __float2half_rn(v.w - __half2float(h3));
        __half2* drow = (__half2*)(dst + (long)row * (2 * Dq * 4));
        drow[2 * g]     = hp0;
        drow[2 * g + 1] = hp1;
        drow[2 * Dq + 2 * g]     = __halves2half2(l0, l1);
        drow[2 * Dq + 2 * g + 1] = __halves2half2(l2, l3);
    }
}

// ---- GEMM: C[b,m,n] = sum_d A[b,m,d]*B[b,n,d]
// aTwoTerm=1: A fp16 [rows, 512] = [h|l], two MMA terms.
// aTwoTerm=0: A fp16 [rows, 256] = h, one MMA term.
// B fp16 [rows, 256] = h.
// epi_hl == 0: C fp32 [.., M, ldC] + bias.   epi_hl == 1: C fp16 h [M, ldC].
__global__ __launch_bounds__(NTHREADS, 2)
void gemm_hl_kernel(const __half* __restrict__ A,
                    const __half* __restrict__ B,
                    void* __restrict__ Cv,
                    int ldC,
                    long strideA, long strideB, long strideC,
                    const float* __restrict__ bias_ptr, int epi_hl, int aTwoTerm)
{
    extern __shared__ __align__(16) char smem[];
    const uint32_t sbase = smem_u32(smem);

    const int tid  = threadIdx.x;
    const int lane = tid & 31;
    const int wid  = tid >> 5;        // 0..7
    const int wm   = wid & 3;         // 4 warps along M (32 rows each)
    const int wn   = wid >> 2;        // 2 warps along N (64 cols each)
    const int m0   = blockIdx.y * BM;
    const int n0   = blockIdx.x * BN;
    const int b    = blockIdx.z;

    const int aK   = aTwoTerm ? K2 : D_;
    const char* Ab = (const char*)(A + (long)b * strideA + (long)m0 * aK);
    const char* Bb = (const char*)(B + (long)b * strideB + (long)n0 * D_);
    const int aRowB = aK * 2;         // 1024 or 512
    const int bRowB = D_ * 2;         // 512
    const int lHalf = D_ * 2;         // 512: l offset within two-term A row

    float acc[2][8][4];
    #pragma unroll
    for (int mi = 0; mi < 2; mi++)
        #pragma unroll
        for (int nf = 0; nf < 8; nf++)
            #pragma unroll
            for (int j = 0; j < 4; j++)
                acc[mi][nf][j] = 0.0f;

    const int nchunk = D_ / 32;       // 8 chunks of 64B per row

    auto issue_stage = [&](int slot, int c) {
        const int kb = c * 64;
        const uint32_t st = sbase + slot * STAGE_BYTES;
        #pragma unroll
        for (int i = 0; i < 2; i++) {
            int q = tid + NTHREADS * i;       // 0..511
            int row = q >> 2, qd = (q & 3) * 16;
            const char* arow = Ab + (long)row * aRowB + kb + qd;
            const char* brow = Bb + (long)row * bRowB + kb + qd;
            uint32_t so = row * ROWB + qd;
            cp16(st + so, arow);                                  // Ah
            if (aTwoTerm) cp16(st + TILE_B + so, arow + lHalf);   // Al
            cp16(st + 2 * TILE_B + so, brow);                     // Bh
        }
        asm volatile("cp.async.commit_group;" ::: "memory");
    };

    issue_stage(0, 0);
    issue_stage(1, 1);

    const uint32_t lmOff = (uint32_t)((lane & 15) * ROWB + (lane >> 4) * 16);
    const uint32_t aOff = (uint32_t)(wm * 32 * ROWB) + lmOff;
    const uint32_t bOff = (uint32_t)(2 * TILE_B + wn * 64 * ROWB) + lmOff;

    for (int c = 0; c < nchunk; c++) {
        if (c == nchunk - 1) {
            asm volatile("cp.async.wait_group 0;" ::: "memory");
        } else {
            asm volatile("cp.async.wait_group 1;" ::: "memory");
        }
        __syncthreads();
        if (c + 2 < nchunk) issue_stage((c + 2) % 3, c + 2);

        const uint32_t st = sbase + (c % 3) * STAGE_BYTES;
        const uint32_t sA = st + aOff;
        const uint32_t sB = st + bOff;

        #pragma unroll
        for (int ks = 0; ks < 2; ks++) {
            const uint32_t ko = ks * 32;   // 16 fp16 = 32B
            uint32_t aH[2][4], aL[2][4], bF[4][4];
            #pragma unroll
            for (int mi = 0; mi < 2; mi++) ldsm4(aH[mi], sA + mi * 16 * ROWB + ko);
            #pragma unroll
            for (int nb = 0; nb < 4; nb++) ldsm4(bF[nb], sB + nb * 16 * ROWB + ko);
            if (aTwoTerm) {
                #pragma unroll
                for (int mi = 0; mi < 2; mi++) ldsm4(aL[mi], sA + TILE_B + mi * 16 * ROWB + ko);
            }

            #pragma unroll
            for (int mi = 0; mi < 2; mi++)
                #pragma unroll
                for (int nf = 0; nf < 8; nf++)
                    mma16816(acc[mi][nf], aH[mi], bF[nf >> 1][nf & 1], bF[nf >> 1][(nf & 1) + 2]);
            if (aTwoTerm) {
                #pragma unroll
                for (int mi = 0; mi < 2; mi++)
                    #pragma unroll
                    for (int nf = 0; nf < 8; nf++)
                        mma16816(acc[mi][nf], aL[mi], bF[nf >> 1][nf & 1], bF[nf >> 1][(nf & 1) + 2]);
            }
        }
    }

    // ---------------- epilogue ----------------
    const int rbase = wm * 32 + (lane >> 2);
    const int cbase = wn * 64 + (lane & 3) * 2;

    if (!epi_hl) {
        float* Cb = (float*)Cv + (long)b * strideC;
        const float bv = bias_ptr ? bias_ptr[0] : 0.0f;
        #pragma unroll
        for (int mi = 0; mi < 2; mi++) {
            #pragma unroll
            for (int nf = 0; nf < 8; nf++) {
                const int r = m0 + rbase + mi * 16;
                const int cc = n0 + cbase + nf * 8;
                float2 v0 = make_float2(acc[mi][nf][0] + bv, acc[mi][nf][1] + bv);
                float2 v1 = make_float2(acc[mi][nf][2] + bv, acc[mi][nf][3] + bv);
                *(float2*)(Cb + (long)r * ldC + cc)       = v0;
                *(float2*)(Cb + (long)(r + 8) * ldC + cc) = v1;
            }
        }
    } else {
        __half* Cb = (__half*)Cv;
        #pragma unroll
        for (int mi = 0; mi < 2; mi++) {
            #pragma unroll
            for (int nf = 0; nf < 8; nf++) {
                const int cc = n0 + cbase + nf * 8;
                #pragma unroll
                for (int half_i = 0; half_i < 2; half_i++) {
                    const int r = m0 + rbase + mi * 16 + half_i * 8;
                    __half2 hp = __floats2half2_rn(acc[mi][nf][2 * half_i + 0],
                                                   acc[mi][nf][2 * half_i + 1]);
                    *(__half2*)(Cb + (long)r * ldC + cc) = hp;
                }
            }
        }
    }
}

extern "C" void kernel_launch(void* const* d_in, const int* in_sizes, int n_in,
                              void* d_out, int out_size)
{
    const float* tensor0 = (const float*)d_in[0];
    const float* tensor1 = (const float*)d_in[1];
    const float* kernelw = (const float*)d_in[2];
    const float* bias    = (const float*)d_in[3];
    float* out = (float*)d_out;

    __half *t0hl, *t1h, *kh, *qt0h;
    cudaGetSymbolAddress((void**)&t0hl, g_t0hl);
    cudaGetSymbolAddress((void**)&t1h, g_t1h);
    cudaGetSymbolAddress((void**)&kh, g_kh);
    cudaGetSymbolAddress((void**)&qt0h, g_qt0h);

    cudaFuncSetAttribute(gemm_hl_kernel,
                         cudaFuncAttributeMaxDynamicSharedMemorySize, SMEM_BYTES);

    const int Dq = D_ / 4;
    {
        int t4a = S_ * N_ * D_ / 4;
        split_kernel<<<(t4a + 255) / 256, 256>>>(tensor0, t0hl, t4a, Dq, 0);
        split_kernel<<<(t4a + 255) / 256, 256>>>(tensor1, t1h, t4a, Dq, 1);
        int t4k = D_ * D_ / 4;
        split_kernel<<<(t4k + 255) / 256, 256>>>(kernelw, kh, t4k, Dq, 1);
    }

    // GEMM1 (2-term): qt0h = fp16( t0 @ kernel^T )
    {
        dim3 grid(D_ / BN, (S_ * N_) / BM, 1);     // (2, 128, 1)
        gemm_hl_kernel<<<grid, NTHREADS, SMEM_BYTES>>>(
            t0hl, kh, qt0h, D_, 0, 0, 0, nullptr, 1, 1);
    }
    // GEMM2 (1-term): out = t1_h @ qt0h^T + bias
    {
        dim3 grid(N_ / BN, N_ / BM, S_);           // (16, 16, 8)
        gemm_hl_kernel<<<grid, NTHREADS, SMEM_BYTES>>>(
            t1h, qt0h, out, N_,
            (long)N_ * D_, (long)N_ * D_, (long)N_ * N_, bias, 0, 0);
    }
}

// round 11
// speedup vs baseline: 2.2771x; 1.2434x over previous
#include <cuda_runtime.h>
#include <cuda_fp16.h>
#include <cstdint>

// Problem: S=8, N=2048, D=256
//   qt0[s,j,d] = sum_e tensor0[s,j,e] * kernel[d,e]
//   out[s,i,j] = sum_d tensor1[s,i,d] * qt0[s,j,d] + bias
//
// All-fp16 h-only pipeline (4 independent ~2^-12 rounding sources, ~4.2e-4 rms):
//   GEMM1: qt0_h = fp16( t0_h @ k_h^T )
//   GEMM2: out   = t1_h @ qt0_h^T + bias   (fp32 accum)
// mma.sync.m16n8k16.f16 (sm_103 base ISA), 3-stage cp.async, 1 barrier/chunk,
// K-chunk = 64 fp16 (128B rows) -> only 4 barriers per CTA.

#define BM 128
#define BN 128
#define NTHREADS 256
#define ROWB 144                       // 128B data + 16B pad (conflict-free ldmatrix)
#define TILE_B (128 * ROWB)            // 18432
#define STAGE_BYTES (2 * TILE_B)       // Ah, Bh
#define SMEM_BYTES (3 * STAGE_BYTES)   // 110592 -> 2 CTAs/SM (221KB of 227KB)

static const int S_ = 8;
static const int N_ = 2048;
static const int D_ = 256;

// device scratch (no allocs): 8 + 8 + 0.125 + 8 MB
__device__ __half g_t0h[8 * 2048 * 256];
__device__ __half g_t1h[8 * 2048 * 256];
__device__ __half g_kh[256 * 256];
__device__ __half g_qt0h[8 * 2048 * 256];

__device__ __forceinline__ uint32_t smem_u32(const void* p) {
    uint32_t a;
    asm("{ .reg .u64 t; cvta.to.shared.u64 t, %1; cvt.u32.u64 %0, t; }" : "=r"(a) : "l"(p));
    return a;
}
__device__ __forceinline__ void ldsm4(uint32_t* r, uint32_t addr) {
    asm volatile("ldmatrix.sync.aligned.m8n8.x4.shared.b16 {%0,%1,%2,%3}, [%4];"
                 : "=r"(r[0]), "=r"(r[1]), "=r"(r[2]), "=r"(r[3]) : "r"(addr));
}
__device__ __forceinline__ void mma16816(float* c, const uint32_t* a, uint32_t b0, uint32_t b1) {
    asm volatile("mma.sync.aligned.m16n8k16.row.col.f32.f16.f16.f32 "
                 "{%0,%1,%2,%3}, {%4,%5,%6,%7}, {%8,%9}, {%0,%1,%2,%3};"
                 : "+f"(c[0]), "+f"(c[1]), "+f"(c[2]), "+f"(c[3])
                 : "r"(a[0]), "r"(a[1]), "r"(a[2]), "r"(a[3]), "r"(b0), "r"(b1));
}
__device__ __forceinline__ void cp16(uint32_t dst, const void* src) {
    asm volatile("cp.async.cg.shared.global [%0], [%1], 16;" :: "r"(dst), "l"(src));
}

// ---- pre-pass: fp32 [rows, D] -> fp16 h [rows, D] ----
__global__ void to_h_kernel(const float* __restrict__ src,
                            __half* __restrict__ dst, int total4)
{
    int idx = blockIdx.x * blockDim.x + threadIdx.x;
    if (idx >= total4) return;
    float4 v = ((const float4*)src)[idx];
    __half2 p0 = __floats2half2_rn(v.x, v.y);
    __half2 p1 = __floats2half2_rn(v.z, v.w);
    ((__half2*)dst)[2 * idx]     = p0;
    ((__half2*)dst)[2 * idx + 1] = p1;
}

// ---- GEMM: C[b,m,n] = sum_d A[b,m,d]*B[b,n,d]; A,B fp16 [rows, D] ----
// epi_hl == 0: C fp32 [.., M, ldC] + bias.   epi_hl == 1: C fp16 [M, ldC].
__global__ __launch_bounds__(NTHREADS, 2)
void gemm_h_kernel(const __half* __restrict__ A,
                   const __half* __restrict__ B,
                   void* __restrict__ Cv,
                   int ldC,
                   long strideA, long strideB, long strideC,
                   const float* __restrict__ bias_ptr, int epi_hl)
{
    extern __shared__ __align__(16) char smem[];
    const uint32_t sbase = smem_u32(smem);

    const int tid  = threadIdx.x;
    const int lane = tid & 31;
    const int wid  = tid >> 5;        // 0..7
    const int wm   = wid & 3;         // 4 warps along M (32 rows each)
    const int wn   = wid >> 2;        // 2 warps along N (64 cols each)
    const int m0   = blockIdx.y * BM;
    const int n0   = blockIdx.x * BN;
    const int b    = blockIdx.z;

    const char* Ab = (const char*)(A + (long)b * strideA + (long)m0 * D_);
    const char* Bb = (const char*)(B + (long)b * strideB + (long)n0 * D_);
    const int rowBytes = D_ * 2;      // 512

    float acc[2][8][4];
    #pragma unroll
    for (int mi = 0; mi < 2; mi++)
        #pragma unroll
        for (int nf = 0; nf < 8; nf++)
            #pragma unroll
            for (int j = 0; j < 4; j++)
                acc[mi][nf][j] = 0.0f;

    const int nchunk = D_ / 64;       // 4 chunks of 128B per row

    auto issue_stage = [&](int slot, int c) {
        const int kb = c * 128;
        const uint32_t st = sbase + slot * STAGE_BYTES;
        #pragma unroll
        for (int i = 0; i < 4; i++) {
            int q = tid + NTHREADS * i;       // 0..1023
            int row = q >> 3, qd = (q & 7) * 16;
            uint32_t so = row * ROWB + qd;
            cp16(st + so,          Ab + (long)row * rowBytes + kb + qd);   // Ah
            cp16(st + TILE_B + so, Bb + (long)row * rowBytes + kb + qd);   // Bh
        }
        asm volatile("cp.async.commit_group;" ::: "memory");
    };

    issue_stage(0, 0);
    issue_stage(1, 1);

    const uint32_t lmOff = (uint32_t)((lane & 15) * ROWB + (lane >> 4) * 16);
    const uint32_t aOff = (uint32_t)(wm * 32 * ROWB) + lmOff;
    const uint32_t bOff = (uint32_t)(TILE_B + wn * 64 * ROWB) + lmOff;

    for (int c = 0; c < nchunk; c++) {
        if (c == nchunk - 1) {
            asm volatile("cp.async.wait_group 0;" ::: "memory");
        } else {
            asm volatile("cp.async.wait_group 1;" ::: "memory");
        }
        __syncthreads();
        if (c + 2 < nchunk) issue_stage((c + 2) % 3, c + 2);

        const uint32_t st = sbase + (c % 3) * STAGE_BYTES;
        const uint32_t sA = st + aOff;
        const uint32_t sB = st + bOff;

        #pragma unroll
        for (int ks = 0; ks < 4; ks++) {
            const uint32_t ko = ks * 32;   // 16 fp16 = 32B
            uint32_t aF[2][4], bF[4][4];
            #pragma unroll
            for (int mi = 0; mi < 2; mi++) ldsm4(aF[mi], sA + mi * 16 * ROWB + ko);
            #pragma unroll
            for (int nb = 0; nb < 4; nb++) ldsm4(bF[nb], sB + nb * 16 * ROWB + ko);

            #pragma unroll
            for (int mi = 0; mi < 2; mi++)
                #pragma unroll
                for (int nf = 0; nf < 8; nf++)
                    mma16816(acc[mi][nf], aF[mi], bF[nf >> 1][nf & 1], bF[nf >> 1][(nf & 1) + 2]);
        }
    }

    // ---------------- epilogue ----------------
    const int rbase = wm * 32 + (lane >> 2);
    const int cbase = wn * 64 + (lane & 3) * 2;

    if (!epi_hl) {
        float* Cb = (float*)Cv + (long)b * strideC;
        const float bv = bias_ptr ? bias_ptr[0] : 0.0f;
        #pragma unroll
        for (int mi = 0; mi < 2; mi++) {
            #pragma unroll
            for (int nf = 0; nf < 8; nf++) {
                const int r = m0 + rbase + mi * 16;
                const int cc = n0 + cbase + nf * 8;
                float2 v0 = make_float2(acc[mi][nf][0] + bv, acc[mi][nf][1] + bv);
                float2 v1 = make_float2(acc[mi][nf][2] + bv, acc[mi][nf][3] + bv);
                *(float2*)(Cb + (long)r * ldC + cc)       = v0;
                *(float2*)(Cb + (long)(r + 8) * ldC + cc) = v1;
            }
        }
    } else {
        __half* Cb = (__half*)Cv;
        #pragma unroll
        for (int mi = 0; mi < 2; mi++) {
            #pragma unroll
            for (int nf = 0; nf < 8; nf++) {
                const int cc = n0 + cbase + nf * 8;
                #pragma unroll
                for (int half_i = 0; half_i < 2; half_i++) {
                    const int r = m0 + rbase + mi * 16 + half_i * 8;
                    __half2 hp = __floats2half2_rn(acc[mi][nf][2 * half_i + 0],
                                                   acc[mi][nf][2 * half_i + 1]);
                    *(__half2*)(Cb + (long)r * ldC + cc) = hp;
                }
            }
        }
    }
}

extern "C" void kernel_launch(void* const* d_in, const int* in_sizes, int n_in,
                              void* d_out, int out_size)
{
    const float* tensor0 = (const float*)d_in[0];
    const float* tensor1 = (const float*)d_in[1];
    const float* kernelw = (const float*)d_in[2];
    const float* bias    = (const float*)d_in[3];
    float* out = (float*)d_out;

    __half *t0h, *t1h, *kh, *qt0h;
    cudaGetSymbolAddress((void**)&t0h, g_t0h);
    cudaGetSymbolAddress((void**)&t1h, g_t1h);
    cudaGetSymbolAddress((void**)&kh, g_kh);
    cudaGetSymbolAddress((void**)&qt0h, g_qt0h);

    cudaFuncSetAttribute(gemm_h_kernel,
                         cudaFuncAttributeMaxDynamicSharedMemorySize, SMEM_BYTES);

    {
        int t4a = S_ * N_ * D_ / 4;
        to_h_kernel<<<(t4a + 255) / 256, 256>>>(tensor0, t0h, t4a);
        to_h_kernel<<<(t4a + 255) / 256, 256>>>(tensor1, t1h, t4a);
        int t4k = D_ * D_ / 4;
        to_h_kernel<<<(t4k + 255) / 256, 256>>>(kernelw, kh, t4k);
    }

    // GEMM1: qt0h = fp16( t0_h @ k_h^T );  M=16384, N'=256
    {
        dim3 grid(D_ / BN, (S_ * N_) / BM, 1);     // (2, 128, 1)
        gemm_h_kernel<<<grid, NTHREADS, SMEM_BYTES>>>(
            t0h, kh, qt0h, D_, 0, 0, 0, nullptr, 1);
    }
    // GEMM2: out = t1_h @ qt0h^T + bias;  2048x2048 x8
    {
        dim3 grid(N_ / BN, N_ / BM, S_);           // (16, 16, 8)
        gemm_h_kernel<<<grid, NTHREADS, SMEM_BYTES>>>(
            t1h, qt0h, out, N_,
            (long)N_ * D_, (long)N_ * D_, (long)N_ * N_, bias, 0);
    }
}

// round 13
// speedup vs baseline: 2.3361x; 1.0259x over previous
#include <cuda_runtime.h>
#include <cuda_fp16.h>
#include <cstdint>

// Problem: S=8, N=2048, D=256
//   qt0[s,j,d] = sum_e tensor0[s,j,e] * kernel[d,e]
//   out[s,i,j] = sum_d tensor1[s,i,d] * qt0[s,j,d] + bias
//
// All-fp16 h-only pipeline (~4.2e-4 rms, threshold 1e-3):
//   GEMM1 (fused cvt): qt0_h = fp16( fp16(t0) @ k_h^T )   [t0 converted in-loader]
//   GEMM2:             out   = t1_h @ qt0_h^T + bias      [fp32 accum]
// mma.sync.m16n8k16.f16 (sm_103 base ISA).

#define NTHREADS 256
#define ROWB 144                       // 128B data + 16B pad (conflict-free ldmatrix)
#define TILE_B (128 * ROWB)            // 18432: one 128-row x 64-fp16 chunk tile

#define G2_STAGE (2 * TILE_B)          // Ah, Bh
#define G2_SMEM  (3 * G2_STAGE)        // 110592

#define G1_BOFF  0
#define G1_AOFF  (4 * TILE_B)          // 73728
#define G1_SMEM  (6 * TILE_B)          // 110592

static const int S_ = 8;
static const int N_ = 2048;
static const int D_ = 256;

__device__ __half g_t1h[8 * 2048 * 256];
__device__ __half g_kh[256 * 256];
__device__ __half g_qt0h[8 * 2048 * 256];

__device__ __forceinline__ uint32_t smem_u32(const void* p) {
    uint32_t a;
    asm("{ .reg .u64 t; cvta.to.shared.u64 t, %1; cvt.u32.u64 %0, t; }" : "=r"(a) : "l"(p));
    return a;
}
__device__ __forceinline__ void ldsm4(uint32_t* r, uint32_t addr) {
    asm volatile("ldmatrix.sync.aligned.m8n8.x4.shared.b16 {%0,%1,%2,%3}, [%4];"
                 : "=r"(r[0]), "=r"(r[1]), "=r"(r[2]), "=r"(r[3]) : "r"(addr));
}
__device__ __forceinline__ void mma16816(float* c, const uint32_t* a, uint32_t b0, uint32_t b1) {
    asm volatile("mma.sync.aligned.m16n8k16.row.col.f32.f16.f16.f32 "
                 "{%0,%1,%2,%3}, {%4,%5,%6,%7}, {%8,%9}, {%0,%1,%2,%3};"
                 : "+f"(c[0]), "+f"(c[1]), "+f"(c[2]), "+f"(c[3])
                 : "r"(a[0]), "r"(a[1]), "r"(a[2]), "r"(a[3]), "r"(b0), "r"(b1));
}
__device__ __forceinline__ void cp16(uint32_t dst, const void* src) {
    asm volatile("cp.async.cg.shared.global [%0], [%1], 16;" :: "r"(dst), "l"(src));
}

// ---- combined pre-pass: t1 (n1 float4s) then kernel (n2 float4s) -> fp16 h ----
__global__ void to_h2_kernel(const float* __restrict__ s1, __half* __restrict__ d1, int n1,
                             const float* __restrict__ s2, __half* __restrict__ d2, int n2)
{
    int idx = blockIdx.x * blockDim.x + threadIdx.x;
    const float* src; __half* dst; int i;
    if (idx < n1) { src = s1; dst = d1; i = idx; }
    else if (idx < n1 + n2) { src = s2; dst = d2; i = idx - n1; }
    else return;
    float4 v = ((const float4*)src)[i];
    ((__half2*)dst)[2 * i]     = __floats2half2_rn(v.x, v.y);
    ((__half2*)dst)[2 * i + 1] = __floats2half2_rn(v.z, v.w);
}

// ---- GEMM1: qt0h[m, n] = fp16( sum_e t0f32[m,e] * kh[n,e] ), M=16384, N'=256 ----
// A converted fp32->fp16 in the loader; B (kernel_h) resident in smem for all K.
__global__ __launch_bounds__(NTHREADS, 1)
void gemm1_kernel(const float* __restrict__ A,       // [16384, 256] fp32
                  const __half* __restrict__ B,      // [256, 256] fp16
                  __half* __restrict__ C)            // [16384, 256] fp16
{
    extern __shared__ __align__(16) char smem[];
    const uint32_t sbase = smem_u32(smem);

    const int tid  = threadIdx.x;
    const int lane = tid & 31;
    const int wid  = tid >> 5;
    const int wm   = wid & 3;          // 4 warps along M (32 rows)
    const int wn   = wid >> 2;         // 2 warps along N (64 cols)
    const int m0   = blockIdx.y * 128;
    const int n0   = blockIdx.x * 128;

    // resident B: 128 rows x 256 fp16, chunked by K (4 chunks x 128B)
    {
        const char* Bb = (const char*)(B + (long)n0 * D_);
        #pragma unroll
        for (int i = 0; i < 16; i++) {
            int q = tid + NTHREADS * i;          // 0..4095
            int row = q >> 5;
            int qq = q & 31;
            int k = qq >> 3, qd = (qq & 7) * 16;
            cp16(sbase + G1_BOFF + k * TILE_B + row * ROWB + qd,
                 Bb + (long)row * 512 + k * 128 + qd);
        }
        asm volatile("cp.async.commit_group;" ::: "memory");
    }

    float acc[2][8][4];
    #pragma unroll
    for (int mi = 0; mi < 2; mi++)
        #pragma unroll
        for (int nf = 0; nf < 8; nf++)
            #pragma unroll
            for (int j = 0; j < 4; j++)
                acc[mi][nf][j] = 0.0f;

    float4 ra[8];
    auto lda = [&](int c) {
        const int kb = c * 64;
        #pragma unroll
        for (int i = 0; i < 8; i++) {
            int idx = tid + NTHREADS * i;
            int row = idx >> 4, g = idx & 15;
            ra[i] = *(const float4*)(A + (long)(m0 + row) * D_ + kb + g * 4);
        }
    };
    auto sta = [&](int buf) {
        #pragma unroll
        for (int i = 0; i < 8; i++) {
            int idx = tid + NTHREADS * i;
            int row = idx >> 4, g = idx & 15;
            char* dstp = smem + G1_AOFF + buf * TILE_B + row * ROWB + g * 8;
            *(__half2*)(dstp)     = __floats2half2_rn(ra[i].x, ra[i].y);
            *(__half2*)(dstp + 4) = __floats2half2_rn(ra[i].z, ra[i].w);
        }
    };

    lda(0);
    sta(0);
    asm volatile("cp.async.wait_group 0;" ::: "memory");   // B ready
    __syncthreads();

    const uint32_t lmOff = (uint32_t)((lane & 15) * ROWB + (lane >> 4) * 16);
    const uint32_t aWarp = (uint32_t)(wm * 32 * ROWB) + lmOff;
    const uint32_t bWarp = (uint32_t)(wn * 64 * ROWB) + lmOff;

    for (int c = 0; c < 4; c++) {
        if (c + 1 < 4) lda(c + 1);

        const uint32_t sA = sbase + G1_AOFF + (c & 1) * TILE_B + aWarp;
        const uint32_t sB = sbase + G1_BOFF + c * TILE_B + bWarp;

        #pragma unroll
        for (int ks = 0; ks < 4; ks++) {
            const uint32_t ko = ks * 32;
            uint32_t aF[2][4], bF[4][4];
            #pragma unroll
            for (int mi = 0; mi < 2; mi++) ldsm4(aF[mi], sA + mi * 16 * ROWB + ko);
            #pragma unroll
            for (int nb = 0; nb < 4; nb++) ldsm4(bF[nb], sB + nb * 16 * ROWB + ko);
            #pragma unroll
            for (int mi = 0; mi < 2; mi++)
                #pragma unroll
                for (int nf = 0; nf < 8; nf++)
                    mma16816(acc[mi][nf], aF[mi], bF[nf >> 1][nf & 1], bF[nf >> 1][(nf & 1) + 2]);
        }

        if (c + 1 < 4) {
            sta((c + 1) & 1);
            __syncthreads();
        }
    }

    const int rbase = wm * 32 + (lane >> 2);
    const int cbase = wn * 64 + (lane & 3) * 2;
    #pragma unroll
    for (int mi = 0; mi < 2; mi++) {
        #pragma unroll
        for (int nf = 0; nf < 8; nf++) {
            const int cc = n0 + cbase + nf * 8;
            #pragma unroll
            for (int hf = 0; hf < 2; hf++) {
                const int r = m0 + rbase + mi * 16 + hf * 8;
                __half2 hp = __floats2half2_rn(acc[mi][nf][2 * hf + 0],
                                               acc[mi][nf][2 * hf + 1]);
                *(__half2*)(C + (long)r * D_ + cc) = hp;
            }
        }
    }
}

// ---- GEMM2 (verbatim R11 core): C[b,m,n] = sum_d A[b,m,d]*B[b,n,d] + bias ----
__global__ __launch_bounds__(NTHREADS, 2)
void gemm2_kernel(const __half* __restrict__ A,
                  const __half* __restrict__ B,
                  float* __restrict__ C,
                  const float* __restrict__ bias_ptr)
{
    extern __shared__ __align__(16) char smem[];
    const uint32_t sbase = smem_u32(smem);

    const int tid  = threadIdx.x;
    const int lane = tid & 31;
    const int wid  = tid >> 5;
    const int wm   = wid & 3;
    const int wn   = wid >> 2;
    const int m0   = blockIdx.y * 128;
    const int n0   = blockIdx.x * 128;
    const int b    = blockIdx.z;

    const char* Ab = (const char*)(A + (long)b * N_ * D_ + (long)m0 * D_);
    const char* Bb = (const char*)(B + (long)b * N_ * D_ + (long)n0 * D_);

    float acc[2][8][4];
    #pragma unroll
    for (int mi = 0; mi < 2; mi++)
        #pragma unroll
        for (int nf = 0; nf < 8; nf++)
            #pragma unroll
            for (int j = 0; j < 4; j++)
                acc[mi][nf][j] = 0.0f;

    const int nchunk = D_ / 64;       // 4 chunks of 128B per row

    auto issue_stage = [&](int slot, int c) {
        const int kb = c * 128;
        const uint32_t st = sbase + slot * G2_STAGE;
        #pragma unroll
        for (int i = 0; i < 4; i++) {
            int q = tid + NTHREADS * i;
            int row = q >> 3, qd = (q & 7) * 16;
            uint32_t so = row * ROWB + qd;
            cp16(st + so,          Ab + (long)row * 512 + kb + qd);
            cp16(st + TILE_B + so, Bb + (long)row * 512 + kb + qd);
        }
        asm volatile("cp.async.commit_group;" ::: "memory");
    };

    issue_stage(0, 0);
    issue_stage(1, 1);

    const uint32_t lmOff = (uint32_t)((lane & 15) * ROWB + (lane >> 4) * 16);
    const uint32_t aOff = (uint32_t)(wm * 32 * ROWB) + lmOff;
    const uint32_t bOff = (uint32_t)(TILE_B + wn * 64 * ROWB) + lmOff;

    for (int c = 0; c < nchunk; c++) {
        if (c == nchunk - 1) {
            asm volatile("cp.async.wait_group 0;" ::: "memory");
        } else {
            asm volatile("cp.async.wait_group 1;" ::: "memory");
        }
        __syncthreads();
        if (c + 2 < nchunk) issue_stage((c + 2) % 3, c + 2);

        const uint32_t st = sbase + (c % 3) * G2_STAGE;
        const uint32_t sA = st + aOff;
        const uint32_t sB = st + bOff;

        #pragma unroll
        for (int ks = 0; ks < 4; ks++) {
            const uint32_t ko = ks * 32;
            uint32_t aF[2][4], bF[4][4];
            #pragma unroll
            for (int mi = 0; mi < 2; mi++) ldsm4(aF[mi], sA + mi * 16 * ROWB + ko);
            #pragma unroll
            for (int nb = 0; nb < 4; nb++) ldsm4(bF[nb], sB + nb * 16 * ROWB + ko);
            #pragma unroll
            for (int mi = 0; mi < 2; mi++)
                #pragma unroll
                for (int nf = 0; nf < 8; nf++)
                    mma16816(acc[mi][nf], aF[mi], bF[nf >> 1][nf & 1], bF[nf >> 1][(nf & 1) + 2]);
        }
    }

    const int rbase = wm * 32 + (lane >> 2);
    const int cbase = wn * 64 + (lane & 3) * 2;
    float* Cb = C + (long)b * N_ * N_;
    const float bv = bias_ptr[0];
    #pragma unroll
    for (int mi = 0; mi < 2; mi++) {
        #pragma unroll
        for (int nf = 0; nf < 8; nf++) {
            const int r = m0 + rbase + mi * 16;
            const int cc = n0 + cbase + nf * 8;
            float2 v0 = make_float2(acc[mi][nf][0] + bv, acc[mi][nf][1] + bv);
            float2 v1 = make_float2(acc[mi][nf][2] + bv, acc[mi][nf][3] + bv);
            *(float2*)(Cb + (long)r * N_ + cc)       = v0;
            *(float2*)(Cb + (long)(r + 8) * N_ + cc) = v1;
        }
    }
}

extern "C" void kernel_launch(void* const* d_in, const int* in_sizes, int n_in,
                              void* d_out, int out_size)
{
    const float* tensor0 = (const float*)d_in[0];
    const float* tensor1 = (const float*)d_in[1];
    const float* kernelw = (const float*)d_in[2];
    const float* bias    = (const float*)d_in[3];
    float* out = (float*)d_out;

    __half *t1h, *kh, *qt0h;
    cudaGetSymbolAddress((void**)&t1h, g_t1h);
    cudaGetSymbolAddress((void**)&kh, g_kh);
    cudaGetSymbolAddress((void**)&qt0h, g_qt0h);

    cudaFuncSetAttribute(gemm1_kernel,
                         cudaFuncAttributeMaxDynamicSharedMemorySize, G1_SMEM);
    cudaFuncSetAttribute(gemm2_kernel,
                         cudaFuncAttributeMaxDynamicSharedMemorySize, G2_SMEM);

    {
        int n1 = S_ * N_ * D_ / 4;
        int n2 = D_ * D_ / 4;
        to_h2_kernel<<<(n1 + n2 + 255) / 256, 256>>>(tensor1, t1h, n1, kernelw, kh, n2);
    }
    {
        dim3 grid(D_ / 128, (S_ * N_) / 128, 1);   // (2, 128, 1)
        gemm1_kernel<<<grid, NTHREADS, G1_SMEM>>>(tensor0, kh, qt0h);
    }
    {
        dim3 grid(N_ / 128, N_ / 128, S_);         // (16, 16, 8)
        gemm2_kernel<<<grid, NTHREADS, G2_SMEM>>>(t1h, qt0h, out, bias);
    }
}